// round 2
// baseline (speedup 1.0000x reference)
#include <cuda_runtime.h>
#include <math.h>
#include <limits.h>
#include <stdint.h>

#define NN 50000
#define FF 128
#define CC 512
#define EE 800000
#define HH 256

#define OFF_NEWX 0
#define OFF_ADJ  (CC*FF)
#define OFF_BATCH (OFF_ADJ + CC*CC)
#define OFF_S    (OFF_BATCH + CC)

// ---------------- device scratch (static, no allocations) ----------------
static __device__ float g_h[(size_t)NN*CC];     // GEMM outputs (<=512 wide)
static __device__ float g_y[(size_t)NN*HH];     // inv-scaled features (<=256 wide)
static __device__ float g_agg[(size_t)NN*HH];   // aggregated features (<=256 wide)
static __device__ int   g_rowptr[NN+1];
static __device__ int   g_deg[NN];
static __device__ int   g_cursor[NN];
static __device__ int   g_csrsrc[EE];
static __device__ float g_inv[NN];
static __device__ float g_hs[NN];
static __device__ float g_invs[NN];
static __device__ float g_score[NN];
static __device__ int   g_cluster[NN];
static __device__ int   g_segkey[CC];
static __device__ int   g_segidx[CC];
static __device__ int   g_cintra[CC];

// ---------------- helpers ----------------
__device__ __forceinline__ int fenc(float f){ int i=__float_as_int(f); return i<0 ? (i^0x7FFFFFFF) : i; }
__device__ __forceinline__ float fdec(int i){ return __int_as_float(i<0 ? (i^0x7FFFFFFF) : i); }

__device__ __forceinline__ unsigned long long pk2(float x, float y){
  unsigned long long r; asm("mov.b64 %0,{%1,%2};":"=l"(r):"f"(x),"f"(y)); return r; }
__device__ __forceinline__ unsigned long long dup2(float x){
  unsigned long long r; asm("mov.b64 %0,{%1,%1};":"=l"(r):"f"(x)); return r; }
__device__ __forceinline__ void fma2(unsigned long long& d, unsigned long long a, unsigned long long b){
  asm("fma.rn.f32x2 %0,%1,%2,%0;":"+l"(d):"l"(a),"l"(b)); }
__device__ __forceinline__ float2 up2(unsigned long long v){
  float2 f; asm("mov.b64 {%0,%1},%2;":"=f"(f.x),"=f"(f.y):"l"(v)); return f; }

// ---------------- setup kernels ----------------
__global__ void k_init(){
  int i=blockIdx.x*blockDim.x+threadIdx.x;
  if(i<NN) g_deg[i]=0;
  if(i<CC){ g_cintra[i]=0; g_segkey[i]=INT_MIN; g_segidx[i]=NN; }
}

__global__ void k_deg(const int* __restrict__ dst){
  int e=blockIdx.x*blockDim.x+threadIdx.x;
  if(e<EE) atomicAdd(&g_deg[dst[e]],1);
}

// single-block exclusive scan of g_deg -> g_rowptr (NN+1 entries)
__global__ void k_scan(){
  __shared__ int sh[256];
  __shared__ int carry;
  int t=threadIdx.x;
  if(t==0) carry=0;
  __syncthreads();
  for(int base=0;base<NN;base+=256){
    int i=base+t;
    int v=(i<NN)?g_deg[i]:0;
    sh[t]=v; __syncthreads();
    int x=v;
    #pragma unroll
    for(int off=1;off<256;off<<=1){
      int tv=(t>=off)?sh[t-off]:0;
      __syncthreads();
      x+=tv; sh[t]=x;
      __syncthreads();
    }
    if(i<NN) g_rowptr[i]=carry + x - v;
    __syncthreads();
    if(t==255) carry += sh[255];
    __syncthreads();
  }
  if(t==0) g_rowptr[NN]=carry;
}

__global__ void k_prep(){
  int i=blockIdx.x*blockDim.x+threadIdx.x;
  if(i<NN){ g_cursor[i]=g_rowptr[i]; g_inv[i]=rsqrtf((float)g_deg[i]+1.0f); }
}

__global__ void k_scatter(const int* __restrict__ src, const int* __restrict__ dst){
  int e=blockIdx.x*blockDim.x+threadIdx.x;
  if(e>=EE) return;
  int d=dst[e];
  int p=atomicAdd(&g_cursor[d],1);
  g_csrsrc[p]=src[e];
}

// ---------------- per-layer kernels ----------------
// y = h * inv[row], vectorized float4. LSH = log2(F/4)
template<int LSH>
__global__ void k_scale(const float* __restrict__ h, float* __restrict__ y, int total4){
  int i=blockIdx.x*blockDim.x+threadIdx.x;
  if(i>=total4) return;
  int node=i>>LSH;
  float w=g_inv[node];
  float4 v=((const float4*)h)[i];
  v.x*=w; v.y*=w; v.z*=w; v.w*=w;
  ((float4*)y)[i]=v;
}

// agg[i] = inv[i] * ( y[i] + sum_{e: dst=i} y[src_e] ) ; V = float4 per lane (F=128 -> 1, F=256 -> 2)
template<int V>
__global__ void k_agg(const float* __restrict__ y, float* __restrict__ out){
  int warp=blockIdx.x*(blockDim.x>>5) + (threadIdx.x>>5);
  int lane=threadIdx.x&31;
  if(warp>=NN) return;
  const float4* y4=(const float4*)y;
  size_t base=(size_t)warp*(32*V);
  float4 acc[V];
  #pragma unroll
  for(int v=0;v<V;v++) acc[v]=y4[base+v*32+lane];
  int s=g_rowptr[warp], e=g_rowptr[warp+1];
  for(int t=s;t<e;t++){
    int src=g_csrsrc[t];
    const float4* r=y4+(size_t)src*(32*V);
    #pragma unroll
    for(int v=0;v<V;v++){
      float4 q=r[v*32+lane];
      acc[v].x+=q.x; acc[v].y+=q.y; acc[v].z+=q.z; acc[v].w+=q.w;
    }
  }
  float w=g_inv[warp];
  float4* o4=(float4*)out;
  #pragma unroll
  for(int v=0;v<V;v++){
    acc[v].x*=w; acc[v].y*=w; acc[v].z*=w; acc[v].w*=w;
    o4[base+v*32+lane]=acc[v];
  }
}

// C[n,K] = relu(A[n,M] @ W[M,K] + bias). BM=BN=128, BK=16, 256 threads, 8x8 microtile, f32x2 FMAs.
__global__ __launch_bounds__(256) void k_gemm(
    const float* __restrict__ A, const float* __restrict__ W,
    const float* __restrict__ bias, float* __restrict__ Cout,
    int n, int M, int K)
{
  __shared__ float As[16][136];
  __shared__ float Ws[16][128];
  const int tid=threadIdx.x, tx=tid&15, ty=tid>>4;
  const int bm=blockIdx.y*128, bn=blockIdx.x*128;
  unsigned long long acc[8][4];
  #pragma unroll
  for(int i=0;i<8;i++)
    #pragma unroll
    for(int j=0;j<4;j++) acc[i][j]=0ull;

  for(int k0=0;k0<M;k0+=16){
    #pragma unroll
    for(int l=0;l<2;l++){
      int idx=tid+l*256;
      int r=idx>>2, c4=idx&3;
      int row=bm+r;
      float4 v = (row<n) ? *(const float4*)&A[(size_t)row*M + k0 + c4*4]
                         : make_float4(0.f,0.f,0.f,0.f);
      As[c4*4+0][r]=v.x; As[c4*4+1][r]=v.y; As[c4*4+2][r]=v.z; As[c4*4+3][r]=v.w;
    }
    #pragma unroll
    for(int l=0;l<2;l++){
      int idx=tid+l*256;
      int r=idx>>5, c4=idx&31;
      float4 v = *(const float4*)&W[(size_t)(k0+r)*K + bn + c4*4];
      *(float4*)&Ws[r][c4*4]=v;
    }
    __syncthreads();
    #pragma unroll
    for(int k=0;k<16;k++){
      unsigned long long b2[4];
      #pragma unroll
      for(int j=0;j<2;j++){
        float4 w=*(float4*)&Ws[k][tx*8+j*4];
        b2[j*2+0]=pk2(w.x,w.y);
        b2[j*2+1]=pk2(w.z,w.w);
      }
      #pragma unroll
      for(int i=0;i<8;i++){
        unsigned long long a2=dup2(As[k][ty*8+i]);
        #pragma unroll
        for(int j=0;j<4;j++) fma2(acc[i][j],a2,b2[j]);
      }
    }
    __syncthreads();
  }
  #pragma unroll
  for(int i=0;i<8;i++){
    int row=bm+ty*8+i;
    if(row<n){
      #pragma unroll
      for(int j=0;j<4;j++){
        float2 v=up2(acc[i][j]);
        int col=bn+tx*8+j*2;
        v.x=fmaxf(v.x+bias[col],0.f);
        v.y=fmaxf(v.y+bias[col+1],0.f);
        *(float2*)&Cout[(size_t)row*K+col]=v;
      }
    }
  }
}

// ---------------- softmax + argmax (warp per row of 512) ----------------
__global__ void k_softmax(const float* __restrict__ h, float* __restrict__ S){
  int warp=blockIdx.x*(blockDim.x>>5)+(threadIdx.x>>5);
  int lane=threadIdx.x&31;
  if(warp>=NN) return;
  const float* row=h+(size_t)warp*CC;
  float vals[16];
  float m=-3.4e38f; int am=0;
  #pragma unroll
  for(int c=0;c<16;c++){
    float v=row[c*32+lane];
    vals[c]=v;
    if(v>m){m=v;am=c*32+lane;}
  }
  #pragma unroll
  for(int off=16;off>0;off>>=1){
    float om=__shfl_down_sync(0xffffffffu,m,off);
    int   oa=__shfl_down_sync(0xffffffffu,am,off);
    if(om>m || (om==m && oa<am)){m=om;am=oa;}
  }
  m=__shfl_sync(0xffffffffu,m,0);
  am=__shfl_sync(0xffffffffu,am,0);
  float s=0.f;
  #pragma unroll
  for(int c=0;c<16;c++){ vals[c]=expf(vals[c]-m); s+=vals[c]; }
  #pragma unroll
  for(int off=16;off>0;off>>=1) s+=__shfl_down_sync(0xffffffffu,s,off);
  s=__shfl_sync(0xffffffffu,s,0);
  float invs=1.f/s;
  float* so=S+(size_t)warp*CC;
  #pragma unroll
  for(int c=0;c<16;c++) so[c*32+lane]=vals[c]*invs;
  if(lane==0) g_cluster[warp]=am;
}

// ---------------- score branch ----------------
__global__ void k_hs(const float* __restrict__ x, const float* __restrict__ Wsm){
  int warp=blockIdx.x*(blockDim.x>>5)+(threadIdx.x>>5);
  int lane=threadIdx.x&31;
  if(warp>=NN) return;
  float4 v=((const float4*)x)[(size_t)warp*32+lane];
  float4 w=((const float4*)Wsm)[lane];
  float d=v.x*w.x+v.y*w.y+v.z*w.z+v.w*w.w;
  #pragma unroll
  for(int off=16;off>0;off>>=1) d+=__shfl_down_sync(0xffffffffu,d,off);
  if(lane==0) g_hs[warp]=d;
}

__global__ void k_degs(){
  int i=blockIdx.x*blockDim.x+threadIdx.x;
  if(i>=NN) return;
  int ci=g_cluster[i];
  int s=g_rowptr[i], e=g_rowptr[i+1], cnt=0;
  for(int t=s;t<e;t++) cnt += (g_cluster[g_csrsrc[t]]==ci) ? 1 : 0;
  g_invs[i]=rsqrtf((float)cnt+1.0f);
  if(cnt>0) atomicAdd(&g_cintra[ci],cnt);
}

__global__ void k_score(const float* __restrict__ bs){
  int i=blockIdx.x*blockDim.x+threadIdx.x;
  if(i>=NN) return;
  int ci=g_cluster[i];
  int s=g_rowptr[i], e=g_rowptr[i+1];
  float sum=0.f;
  for(int t=s;t<e;t++){
    int sn=g_csrsrc[t];
    if(g_cluster[sn]==ci) sum += g_invs[sn]*g_hs[sn];
  }
  float w=g_invs[i];
  g_score[i]=tanhf(w*(sum + w*g_hs[i]) + bs[0]);
}

__global__ void k_segmax(){
  int i=blockIdx.x*blockDim.x+threadIdx.x;
  if(i<NN) atomicMax(&g_segkey[g_cluster[i]], fenc(g_score[i]));
}

__global__ void k_argnode(){
  int i=blockIdx.x*blockDim.x+threadIdx.x;
  if(i>=NN) return;
  int c=g_cluster[i];
  if(fenc(g_score[i]) >= g_segkey[c]) atomicMin(&g_segidx[c], i);
}

// ---------------- outputs ----------------
__global__ void k_newx(const float* __restrict__ x, float* __restrict__ out){
  int c=blockIdx.x;
  int t=threadIdx.x;
  __shared__ float alpha; __shared__ int idx;
  if(t==0){
    alpha = (g_cintra[c]>0) ? fdec(g_segkey[c]) : 0.f;
    idx = min(g_segidx[c], NN-1);
  }
  __syncthreads();
  out[OFF_NEWX + c*FF + t] = x[(size_t)idx*FF + t]*alpha;
}

__global__ void k_adjzero(float* __restrict__ out){
  int i=blockIdx.x*blockDim.x+threadIdx.x;
  if(i<CC*CC+CC) out[OFF_ADJ+i]=0.f;   // covers adj + new_batch (contiguous)
}

__global__ void k_adjfill(const int* __restrict__ src, const int* __restrict__ dst, float* __restrict__ out){
  int e=blockIdx.x*blockDim.x+threadIdx.x;
  if(e>=EE) return;
  int ci=g_cluster[src[e]], cj=g_cluster[dst[e]];
  if(ci!=cj && g_cintra[ci]>0 && g_cintra[cj]>0)
    out[OFF_ADJ + ci*CC + cj]=1.0f;
}

// ---------------- launch ----------------
extern "C" void kernel_launch(void* const* d_in, const int* in_sizes, int n_in,
                              void* d_out, int out_size)
{
  const float* x  =(const float*)d_in[0];
  const int*   ei =(const int*)  d_in[1];
  // d_in[2] = batch (all zeros, unused)
  const float* W1 =(const float*)d_in[3];
  const float* b1 =(const float*)d_in[4];
  const float* W2 =(const float*)d_in[5];
  const float* b2 =(const float*)d_in[6];
  const float* W3 =(const float*)d_in[7];
  const float* b3 =(const float*)d_in[8];
  const float* Wsm=(const float*)d_in[9];
  const float* bs =(const float*)d_in[10];
  float* out=(float*)d_out;

  const int* srcp=ei;
  const int* dstp=ei+EE;

  float *p_h,*p_y,*p_agg;
  cudaGetSymbolAddress((void**)&p_h,  g_h);
  cudaGetSymbolAddress((void**)&p_y,  g_y);
  cudaGetSymbolAddress((void**)&p_agg,g_agg);

  const int TB=256;
  const int gN=(NN+TB-1)/TB;
  const int gE=(EE+TB-1)/TB;
  const int gW=(NN+7)/8;          // warp-per-node kernels (8 warps / 256-thr block)

  // graph prep
  k_init<<<gN,TB>>>();
  k_deg<<<gE,TB>>>(dstp);
  k_scan<<<1,256>>>();
  k_prep<<<gN,TB>>>();
  k_scatter<<<gE,TB>>>(srcp,dstp);

  // layer 1: F=128 -> 256
  k_scale<5><<<(NN*32+TB-1)/TB,TB>>>(x,p_y,NN*32);
  k_agg<1><<<gW,TB>>>(p_y,p_agg);
  k_gemm<<<dim3(2,(NN+127)/128),256>>>(p_agg,W1,b1,p_h,NN,128,256);

  // layer 2: 256 -> 256
  k_scale<6><<<(NN*64+TB-1)/TB,TB>>>(p_h,p_y,NN*64);
  k_agg<2><<<gW,TB>>>(p_y,p_agg);
  k_gemm<<<dim3(2,(NN+127)/128),256>>>(p_agg,W2,b2,p_h,NN,256,256);

  // layer 3: 256 -> 512
  k_scale<6><<<(NN*64+TB-1)/TB,TB>>>(p_h,p_y,NN*64);
  k_agg<2><<<gW,TB>>>(p_y,p_agg);
  k_gemm<<<dim3(4,(NN+127)/128),256>>>(p_agg,W3,b3,p_h,NN,256,512);

  // softmax S + hard cluster assignment
  k_softmax<<<gW,TB>>>(p_h, out+OFF_S);

  // score branch
  k_hs<<<gW,TB>>>(x,Wsm);
  k_degs<<<gN,TB>>>();
  k_score<<<gN,TB>>>(bs);
  k_segmax<<<gN,TB>>>();
  k_argnode<<<gN,TB>>>();

  // outputs
  k_newx<<<CC,FF>>>(x,out);
  k_adjzero<<<(CC*CC+CC+TB-1)/TB,TB>>>(out);
  k_adjfill<<<gE,TB>>>(srcp,dstp,out);
}

// round 5
// speedup vs baseline: 1.7853x; 1.7853x over previous
#include <cuda_runtime.h>
#include <math.h>
#include <limits.h>
#include <stdint.h>

#define NN 50000
#define FF 128
#define CC 512
#define EE 800000
#define HH 256

#define OFF_NEWX 0
#define OFF_ADJ  (CC*FF)
#define OFF_BATCH (OFF_ADJ + CC*CC)
#define OFF_S    (OFF_BATCH + CC)

// ---------------- device scratch (static, no allocations) ----------------
static __device__ float g_h[(size_t)NN*CC];     // GEMM outputs (<=512 wide)
static __device__ float g_y[(size_t)NN*HH];     // inv-scaled features (<=256 wide)
static __device__ float g_Ah[(size_t)NN*HH];    // tf32-hi aggregated features
static __device__ float g_Al[(size_t)NN*HH];    // tf32-lo aggregated features
static __device__ float g_Wth[(size_t)CC*HH];   // transposed tf32-hi weights [Kout][Min]
static __device__ float g_Wtl[(size_t)CC*HH];   // transposed tf32-lo weights
static __device__ int   g_rowptr[NN+1];
static __device__ int   g_deg[NN];
static __device__ int   g_cursor[NN];
static __device__ int   g_csrsrc[EE];
static __device__ float g_inv[NN];
static __device__ float g_hs[NN];
static __device__ float g_invs[NN];
static __device__ float g_score[NN];
static __device__ int   g_cluster[NN];
static __device__ int   g_segkey[CC];
static __device__ int   g_segidx[CC];
static __device__ int   g_cintra[CC];
static __device__ int   g_part[256];

// ---------------- helpers ----------------
__device__ __forceinline__ int fenc(float f){ int i=__float_as_int(f); return i<0 ? (i^0x7FFFFFFF) : i; }
__device__ __forceinline__ float fdec(int i){ return __int_as_float(i<0 ? (i^0x7FFFFFFF) : i); }

__device__ __forceinline__ float to_tf32(float a){
  float r; asm("cvt.rna.tf32.f32 %0,%1;":"=f"(r):"f"(a)); return r;
}

// mma.sync m16n8k8 tf32: D += A*B (row.col), accumulate in place
__device__ __forceinline__ void mma8(float* c, const uint32_t* a, uint32_t b0, uint32_t b1){
  asm volatile(
    "mma.sync.aligned.m16n8k8.row.col.f32.tf32.tf32.f32 "
    "{%0,%1,%2,%3},{%4,%5,%6,%7},{%8,%9},{%0,%1,%2,%3};"
    : "+f"(c[0]),"+f"(c[1]),"+f"(c[2]),"+f"(c[3])
    : "r"(a[0]),"r"(a[1]),"r"(a[2]),"r"(a[3]),"r"(b0),"r"(b1));
}

// ---------------- setup kernels ----------------
__global__ void k_init(){
  int i=blockIdx.x*blockDim.x+threadIdx.x;
  if(i<NN) g_deg[i]=0;
  if(i<CC){ g_cintra[i]=0; g_segkey[i]=INT_MIN; g_segidx[i]=NN; }
}

__global__ void k_deg(const int* __restrict__ dst){
  int e=blockIdx.x*blockDim.x+threadIdx.x;
  if(e<EE) atomicAdd(&g_deg[dst[e]],1);
}

// 3-phase exclusive scan of g_deg -> g_rowptr
__global__ void k_scan1(){
  int b=blockIdx.x, t=threadIdx.x, i=b*256+t;
  int v=(i<NN)?g_deg[i]:0;
  int x=v;
  #pragma unroll
  for(int off=1;off<32;off<<=1){
    int y=__shfl_up_sync(0xffffffffu,x,off);
    if((t&31)>=off) x+=y;
  }
  __shared__ int ws[8];
  if((t&31)==31) ws[t>>5]=x;
  __syncthreads();
  if(t==0){ int s=0; for(int j=0;j<8;j++){int tmp=ws[j]; ws[j]=s; s+=tmp;} g_part[b]=s; }
  __syncthreads();
  if(i<NN) g_rowptr[i]= x - v + ws[t>>5];
}
__global__ void k_scan2(int nblk){
  int t=threadIdx.x;
  __shared__ int sh[256];
  sh[t]=(t<nblk)?g_part[t]:0;
  __syncthreads();
  if(t==0){ int s=0; for(int j=0;j<nblk;j++){int tmp=sh[j]; sh[j]=s; s+=tmp;} g_rowptr[NN]=s; }
  __syncthreads();
  if(t<nblk) g_part[t]=sh[t];
}
__global__ void k_scan3(){
  int i=blockIdx.x*blockDim.x+threadIdx.x;
  if(i<NN) g_rowptr[i]+=g_part[i>>8];
}

__global__ void k_prep(){
  int i=blockIdx.x*blockDim.x+threadIdx.x;
  if(i<NN){ g_cursor[i]=g_rowptr[i]; g_inv[i]=rsqrtf((float)g_deg[i]+1.0f); }
}

__global__ void k_scatter(const int* __restrict__ src, const int* __restrict__ dst){
  int e=blockIdx.x*blockDim.x+threadIdx.x;
  if(e>=EE) return;
  int d=dst[e];
  int p=atomicAdd(&g_cursor[d],1);
  g_csrsrc[p]=src[e];
}

// ---------------- per-layer kernels ----------------
// y = h * inv[row]
template<int LSH>
__global__ void k_scale(const float* __restrict__ h, float* __restrict__ y, int total4){
  int i=blockIdx.x*blockDim.x+threadIdx.x;
  if(i>=total4) return;
  int node=i>>LSH;
  float w=g_inv[node];
  float4 v=((const float4*)h)[i];
  v.x*=w; v.y*=w; v.z*=w; v.w*=w;
  ((float4*)y)[i]=v;
}

// agg[i] = inv[i]*(y[i] + sum y[src]); fused tf32 hi/lo split output
template<int V>
__global__ void k_agg(const float* __restrict__ y, float* __restrict__ ah, float* __restrict__ al){
  int warp=blockIdx.x*(blockDim.x>>5) + (threadIdx.x>>5);
  int lane=threadIdx.x&31;
  if(warp>=NN) return;
  const float4* y4=(const float4*)y;
  size_t base=(size_t)warp*(32*V);
  float4 acc[V];
  #pragma unroll
  for(int v=0;v<V;v++) acc[v]=y4[base+v*32+lane];
  int s=g_rowptr[warp], e=g_rowptr[warp+1];
  for(int t=s;t<e;t++){
    int src=g_csrsrc[t];
    const float4* r=y4+(size_t)src*(32*V);
    #pragma unroll
    for(int v=0;v<V;v++){
      float4 q=r[v*32+lane];
      acc[v].x+=q.x; acc[v].y+=q.y; acc[v].z+=q.z; acc[v].w+=q.w;
    }
  }
  float w=g_inv[warp];
  float4* ah4=(float4*)ah; float4* al4=(float4*)al;
  #pragma unroll
  for(int v=0;v<V;v++){
    float f[4]={acc[v].x*w, acc[v].y*w, acc[v].z*w, acc[v].w*w};
    float4 hi,lo;
    hi.x=to_tf32(f[0]); lo.x=to_tf32(f[0]-hi.x);
    hi.y=to_tf32(f[1]); lo.y=to_tf32(f[1]-hi.y);
    hi.z=to_tf32(f[2]); lo.z=to_tf32(f[2]-hi.z);
    hi.w=to_tf32(f[3]); lo.w=to_tf32(f[3]-hi.w);
    ah4[base+v*32+lane]=hi;
    al4[base+v*32+lane]=lo;
  }
}

// transpose + split W[Min][Kout] -> Wt_hi/Wt_lo [Kout][Min]
__global__ void k_wsplit(const float* __restrict__ W, int Min, int Kout){
  int idx=blockIdx.x*blockDim.x+threadIdx.x;
  if(idx>=Min*Kout) return;
  int m=idx/Kout, nk=idx-m*Kout;
  float w=W[idx];
  float hi=to_tf32(w);
  float lo=to_tf32(w-hi);
  g_Wth[(size_t)nk*Min+m]=hi;
  g_Wtl[(size_t)nk*Min+m]=lo;
}

// ---------------- tf32 split-3 mma.sync GEMM ----------------
// C[128 rows x 64 cols per CTA] = relu(A@W + bias)
// 8 warps: 4 (m) x 2 (n); warp tile 32x32; K chunks of 32, kslices of 8.
#define PAD 36
__global__ __launch_bounds__(256) void k_mma(
    const float* __restrict__ Ah, const float* __restrict__ Al,
    const float* __restrict__ Bh, const float* __restrict__ Bl,
    const float* __restrict__ bias, float* __restrict__ C,
    int n, int Min, int Kout)
{
  extern __shared__ float sm[];
  float* As_h = sm;                    // 128*PAD
  float* As_l = As_h + 128*PAD;
  float* Bs_h = As_l + 128*PAD;        // 64*PAD
  float* Bs_l = Bs_h + 64*PAD;

  int tid=threadIdx.x, lane=tid&31, wid=tid>>5;
  int wm = wid&3, wn = wid>>2;         // 4x2 warp grid
  int bm = blockIdx.y*128, bn = blockIdx.x*64;

  float acc[2][4][4];
  #pragma unroll
  for(int a=0;a<2;a++)
    #pragma unroll
    for(int b=0;b<4;b++)
      #pragma unroll
      for(int c=0;c<4;c++) acc[a][b][c]=0.f;

  for(int k0=0;k0<Min;k0+=32){
    #pragma unroll
    for(int it=0;it<4;it++){
      int i=tid+it*256; int r=i>>3, c4=(i&7)*4;
      int grow=bm+r;
      float4 vh=make_float4(0.f,0.f,0.f,0.f), vl=vh;
      if(grow<n){
        vh=*(const float4*)&Ah[(size_t)grow*Min+k0+c4];
        vl=*(const float4*)&Al[(size_t)grow*Min+k0+c4];
      }
      *(float4*)&As_h[r*PAD+c4]=vh;
      *(float4*)&As_l[r*PAD+c4]=vl;
    }
    #pragma unroll
    for(int it=0;it<2;it++){
      int i=tid+it*256; int r=i>>3, c4=(i&7)*4;
      int brow=bn+r;
      *(float4*)&Bs_h[r*PAD+c4]=*(const float4*)&Bh[(size_t)brow*Min+k0+c4];
      *(float4*)&Bs_l[r*PAD+c4]=*(const float4*)&Bl[(size_t)brow*Min+k0+c4];
    }
    __syncthreads();
    #pragma unroll
    for(int ks=0;ks<4;ks++){
      int kk=ks*8;
      uint32_t afh[2][4], afl[2][4];
      int ar = wm*32 + (lane>>2), ac = kk + (lane&3);
      #pragma unroll
      for(int mf=0;mf<2;mf++){
        int r0 = ar + mf*16;
        afh[mf][0]=__float_as_uint(As_h[r0*PAD+ac]);
        afh[mf][1]=__float_as_uint(As_h[(r0+8)*PAD+ac]);
        afh[mf][2]=__float_as_uint(As_h[r0*PAD+ac+4]);
        afh[mf][3]=__float_as_uint(As_h[(r0+8)*PAD+ac+4]);
        afl[mf][0]=__float_as_uint(As_l[r0*PAD+ac]);
        afl[mf][1]=__float_as_uint(As_l[(r0+8)*PAD+ac]);
        afl[mf][2]=__float_as_uint(As_l[r0*PAD+ac+4]);
        afl[mf][3]=__float_as_uint(As_l[(r0+8)*PAD+ac+4]);
      }
      #pragma unroll
      for(int nf=0;nf<4;nf++){
        int bn_r = wn*32 + nf*8 + (lane>>2);
        int bk = kk + (lane&3);
        uint32_t bh0=__float_as_uint(Bs_h[bn_r*PAD+bk]);
        uint32_t bh1=__float_as_uint(Bs_h[bn_r*PAD+bk+4]);
        uint32_t bl0=__float_as_uint(Bs_l[bn_r*PAD+bk]);
        uint32_t bl1=__float_as_uint(Bs_l[bn_r*PAD+bk+4]);
        #pragma unroll
        for(int mf=0;mf<2;mf++){
          mma8(acc[mf][nf], afh[mf], bh0, bh1);
          mma8(acc[mf][nf], afh[mf], bl0, bl1);
          mma8(acc[mf][nf], afl[mf], bh0, bh1);
        }
      }
    }
    __syncthreads();
  }

  // epilogue: bias + relu, float2 stores
  #pragma unroll
  for(int mf=0;mf<2;mf++){
    int row0 = bm + wm*32 + mf*16 + (lane>>2);
    #pragma unroll
    for(int nf=0;nf<4;nf++){
      int col = bn + wn*32 + nf*8 + (lane&3)*2;
      float b0v=bias[col], b1v=bias[col+1];
      if(row0<n){
        float2 v; v.x=fmaxf(acc[mf][nf][0]+b0v,0.f); v.y=fmaxf(acc[mf][nf][1]+b1v,0.f);
        *(float2*)&C[(size_t)row0*Kout+col]=v;
      }
      if(row0+8<n){
        float2 v; v.x=fmaxf(acc[mf][nf][2]+b0v,0.f); v.y=fmaxf(acc[mf][nf][3]+b1v,0.f);
        *(float2*)&C[(size_t)(row0+8)*Kout+col]=v;
      }
    }
  }
}
#define MMA_SMEM ((2*128*PAD + 2*64*PAD)*4)

// ---------------- softmax + argmax (warp per row of 512) ----------------
__global__ void k_softmax(const float* __restrict__ h, float* __restrict__ S){
  int warp=blockIdx.x*(blockDim.x>>5)+(threadIdx.x>>5);
  int lane=threadIdx.x&31;
  if(warp>=NN) return;
  const float* row=h+(size_t)warp*CC;
  float vals[16];
  float m=-3.4e38f; int am=0;
  #pragma unroll
  for(int c=0;c<16;c++){
    float v=row[c*32+lane];
    vals[c]=v;
    if(v>m){m=v;am=c*32+lane;}
  }
  #pragma unroll
  for(int off=16;off>0;off>>=1){
    float om=__shfl_down_sync(0xffffffffu,m,off);
    int   oa=__shfl_down_sync(0xffffffffu,am,off);
    if(om>m || (om==m && oa<am)){m=om;am=oa;}
  }
  m=__shfl_sync(0xffffffffu,m,0);
  am=__shfl_sync(0xffffffffu,am,0);
  float s=0.f;
  #pragma unroll
  for(int c=0;c<16;c++){ vals[c]=expf(vals[c]-m); s+=vals[c]; }
  #pragma unroll
  for(int off=16;off>0;off>>=1) s+=__shfl_down_sync(0xffffffffu,s,off);
  s=__shfl_sync(0xffffffffu,s,0);
  float invs=1.f/s;
  float* so=S+(size_t)warp*CC;
  #pragma unroll
  for(int c=0;c<16;c++) so[c*32+lane]=vals[c]*invs;
  if(lane==0) g_cluster[warp]=am;
}

// ---------------- score branch ----------------
__global__ void k_hs(const float* __restrict__ x, const float* __restrict__ Wsm){
  int warp=blockIdx.x*(blockDim.x>>5)+(threadIdx.x>>5);
  int lane=threadIdx.x&31;
  if(warp>=NN) return;
  float4 v=((const float4*)x)[(size_t)warp*32+lane];
  float4 w=((const float4*)Wsm)[lane];
  float d=v.x*w.x+v.y*w.y+v.z*w.z+v.w*w.w;
  #pragma unroll
  for(int off=16;off>0;off>>=1) d+=__shfl_down_sync(0xffffffffu,d,off);
  if(lane==0) g_hs[warp]=d;
}

__global__ void k_degs(){
  int i=blockIdx.x*blockDim.x+threadIdx.x;
  if(i>=NN) return;
  int ci=g_cluster[i];
  int s=g_rowptr[i], e=g_rowptr[i+1], cnt=0;
  for(int t=s;t<e;t++) cnt += (g_cluster[g_csrsrc[t]]==ci) ? 1 : 0;
  g_invs[i]=rsqrtf((float)cnt+1.0f);
  if(cnt>0) atomicAdd(&g_cintra[ci],cnt);
}

__global__ void k_score(const float* __restrict__ bs){
  int i=blockIdx.x*blockDim.x+threadIdx.x;
  if(i>=NN) return;
  int ci=g_cluster[i];
  int s=g_rowptr[i], e=g_rowptr[i+1];
  float sum=0.f;
  for(int t=s;t<e;t++){
    int sn=g_csrsrc[t];
    if(g_cluster[sn]==ci) sum += g_invs[sn]*g_hs[sn];
  }
  float w=g_invs[i];
  g_score[i]=tanhf(w*(sum + w*g_hs[i]) + bs[0]);
}

__global__ void k_segmax(){
  int i=blockIdx.x*blockDim.x+threadIdx.x;
  if(i<NN) atomicMax(&g_segkey[g_cluster[i]], fenc(g_score[i]));
}

__global__ void k_argnode(){
  int i=blockIdx.x*blockDim.x+threadIdx.x;
  if(i>=NN) return;
  int c=g_cluster[i];
  if(fenc(g_score[i]) >= g_segkey[c]) atomicMin(&g_segidx[c], i);
}

// ---------------- outputs ----------------
__global__ void k_newx(const float* __restrict__ x, float* __restrict__ out){
  int c=blockIdx.x;
  int t=threadIdx.x;
  __shared__ float alpha; __shared__ int idx;
  if(t==0){
    alpha = (g_cintra[c]>0) ? fdec(g_segkey[c]) : 0.f;
    idx = min(g_segidx[c], NN-1);
  }
  __syncthreads();
  out[OFF_NEWX + c*FF + t] = x[(size_t)idx*FF + t]*alpha;
}

__global__ void k_adjzero(float* __restrict__ out){
  int i=blockIdx.x*blockDim.x+threadIdx.x;
  if(i<CC*CC+CC) out[OFF_ADJ+i]=0.f;
}

__global__ void k_adjfill(const int* __restrict__ src, const int* __restrict__ dst, float* __restrict__ out){
  int e=blockIdx.x*blockDim.x+threadIdx.x;
  if(e>=EE) return;
  int ci=g_cluster[src[e]], cj=g_cluster[dst[e]];
  if(ci!=cj && g_cintra[ci]>0 && g_cintra[cj]>0)
    out[OFF_ADJ + ci*CC + cj]=1.0f;
}

// ---------------- launch ----------------
extern "C" void kernel_launch(void* const* d_in, const int* in_sizes, int n_in,
                              void* d_out, int out_size)
{
  const float* x  =(const float*)d_in[0];
  const int*   ei =(const int*)  d_in[1];
  const float* W1 =(const float*)d_in[3];
  const float* b1 =(const float*)d_in[4];
  const float* W2 =(const float*)d_in[5];
  const float* b2 =(const float*)d_in[6];
  const float* W3 =(const float*)d_in[7];
  const float* b3 =(const float*)d_in[8];
  const float* Wsm=(const float*)d_in[9];
  const float* bs =(const float*)d_in[10];
  float* out=(float*)d_out;

  const int* srcp=ei;
  const int* dstp=ei+EE;

  float *p_h,*p_y,*p_ah,*p_al,*p_wh,*p_wl;
  cudaGetSymbolAddress((void**)&p_h,  g_h);
  cudaGetSymbolAddress((void**)&p_y,  g_y);
  cudaGetSymbolAddress((void**)&p_ah, g_Ah);
  cudaGetSymbolAddress((void**)&p_al, g_Al);
  cudaGetSymbolAddress((void**)&p_wh, g_Wth);
  cudaGetSymbolAddress((void**)&p_wl, g_Wtl);

  cudaFuncSetAttribute(k_mma, cudaFuncAttributeMaxDynamicSharedMemorySize, MMA_SMEM);

  const int TB=256;
  const int gN=(NN+TB-1)/TB;       // 196
  const int gE=(EE+TB-1)/TB;
  const int gW=(NN+7)/8;
  const int gM=(NN+127)/128;       // 391

  // graph prep
  k_init<<<gN,TB>>>();
  k_deg<<<gE,TB>>>(dstp);
  k_scan1<<<gN,TB>>>();
  k_scan2<<<1,256>>>(gN);
  k_scan3<<<gN,TB>>>();
  k_prep<<<gN,TB>>>();
  k_scatter<<<gE,TB>>>(srcp,dstp);

  // layer 1: F=128 -> 256
  k_wsplit<<<(128*256+TB-1)/TB,TB>>>(W1,128,256);
  k_scale<5><<<(NN*32+TB-1)/TB,TB>>>(x,p_y,NN*32);
  k_agg<1><<<gW,TB>>>(p_y,p_ah,p_al);
  k_mma<<<dim3(4,gM),256,MMA_SMEM>>>(p_ah,p_al,p_wh,p_wl,b1,p_h,NN,128,256);

  // layer 2: 256 -> 256
  k_wsplit<<<(256*256+TB-1)/TB,TB>>>(W2,256,256);
  k_scale<6><<<(NN*64+TB-1)/TB,TB>>>(p_h,p_y,NN*64);
  k_agg<2><<<gW,TB>>>(p_y,p_ah,p_al);
  k_mma<<<dim3(4,gM),256,MMA_SMEM>>>(p_ah,p_al,p_wh,p_wl,b2,p_h,NN,256,256);

  // layer 3: 256 -> 512
  k_wsplit<<<(256*512+TB-1)/TB,TB>>>(W3,256,512);
  k_scale<6><<<(NN*64+TB-1)/TB,TB>>>(p_h,p_y,NN*64);
  k_agg<2><<<gW,TB>>>(p_y,p_ah,p_al);
  k_mma<<<dim3(8,gM),256,MMA_SMEM>>>(p_ah,p_al,p_wh,p_wl,b3,p_h,NN,256,512);

  // softmax S + hard cluster assignment
  k_softmax<<<gW,TB>>>(p_h, out+OFF_S);

  // score branch
  k_hs<<<gW,TB>>>(x,Wsm);
  k_degs<<<gN,TB>>>();
  k_score<<<gN,TB>>>(bs);
  k_segmax<<<gN,TB>>>();
  k_argnode<<<gN,TB>>>();

  // outputs
  k_newx<<<CC,FF>>>(x,out);
  k_adjzero<<<(CC*CC+CC+TB-1)/TB,TB>>>(out);
  k_adjfill<<<gE,TB>>>(srcp,dstp,out);
}

// round 6
// speedup vs baseline: 2.1316x; 1.1940x over previous
#include <cuda_runtime.h>
#include <math.h>
#include <limits.h>
#include <stdint.h>

#define NN 50000
#define FF 128
#define CC 512
#define EE 800000
#define HH 256

#define OFF_NEWX 0
#define OFF_ADJ  (CC*FF)
#define OFF_BATCH (OFF_ADJ + CC*CC)
#define OFF_S    (OFF_BATCH + CC)

// ---------------- device scratch (static, no allocations) ----------------
static __device__ float g_h[(size_t)NN*CC];     // GEMM outputs (<=512 wide)
static __device__ float g_Ah[(size_t)NN*HH];    // tf32-hi aggregated features
static __device__ float g_Al[(size_t)NN*HH];    // tf32-lo aggregated features
static __device__ float g_Wth[(size_t)CC*HH];   // transposed tf32-hi weights [Kout][Min]
static __device__ float g_Wtl[(size_t)CC*HH];   // transposed tf32-lo weights
static __device__ int   g_rowptr[NN+1];
static __device__ int   g_deg[NN];
static __device__ int   g_cursor[NN];
static __device__ int   g_csrsrc[EE];
static __device__ float g_inv[NN];
static __device__ float g_hs[NN];
static __device__ float g_invs[NN];
static __device__ float g_score[NN];
static __device__ int   g_cluster[NN];
static __device__ int   g_segkey[CC];
static __device__ int   g_segidx[CC];
static __device__ int   g_cintra[CC];
static __device__ int   g_part[256];

// ---------------- helpers ----------------
__device__ __forceinline__ int fenc(float f){ int i=__float_as_int(f); return i<0 ? (i^0x7FFFFFFF) : i; }
__device__ __forceinline__ float fdec(int i){ return __int_as_float(i<0 ? (i^0x7FFFFFFF) : i); }

__device__ __forceinline__ float to_tf32(float a){
  float r; asm("cvt.rna.tf32.f32 %0,%1;":"=f"(r):"f"(a)); return r;
}

__device__ __forceinline__ uint32_t smem_u32(const void* p){
  uint32_t a; asm("{ .reg .u64 t; cvta.to.shared.u64 t, %1; cvt.u32.u64 %0, t; }":"=r"(a):"l"(p)); return a;
}

// cp.async 16B with zero-fill when srcsz==0
__device__ __forceinline__ void cpa16(uint32_t s, const void* g, uint32_t srcsz){
  asm volatile("cp.async.ca.shared.global [%0], [%1], 16, %2;"::"r"(s),"l"(g),"r"(srcsz));
}
__device__ __forceinline__ void cpa16f(uint32_t s, const void* g){
  asm volatile("cp.async.ca.shared.global [%0], [%1], 16;"::"r"(s),"l"(g));
}
#define CPA_COMMIT() asm volatile("cp.async.commit_group;")
#define CPA_WAIT0()  asm volatile("cp.async.wait_group 0;":::"memory")

// mma.sync m16n8k8 tf32: D += A*B (row.col), accumulate in place
__device__ __forceinline__ void mma8(float* c, const uint32_t* a, uint32_t b0, uint32_t b1){
  asm volatile(
    "mma.sync.aligned.m16n8k8.row.col.f32.tf32.tf32.f32 "
    "{%0,%1,%2,%3},{%4,%5,%6,%7},{%8,%9},{%0,%1,%2,%3};"
    : "+f"(c[0]),"+f"(c[1]),"+f"(c[2]),"+f"(c[3])
    : "r"(a[0]),"r"(a[1]),"r"(a[2]),"r"(a[3]),"r"(b0),"r"(b1));
}

// ---------------- setup kernels ----------------
__global__ void k_init(){
  int i=blockIdx.x*blockDim.x+threadIdx.x;
  if(i<NN) g_deg[i]=0;
  if(i<CC){ g_cintra[i]=0; g_segkey[i]=INT_MIN; g_segidx[i]=NN; }
}

__global__ void k_deg(const int* __restrict__ dst){
  int e=blockIdx.x*blockDim.x+threadIdx.x;
  if(e<EE) atomicAdd(&g_deg[dst[e]],1);
}

// 3-phase exclusive scan of g_deg -> g_rowptr
__global__ void k_scan1(){
  int b=blockIdx.x, t=threadIdx.x, i=b*256+t;
  int v=(i<NN)?g_deg[i]:0;
  int x=v;
  #pragma unroll
  for(int off=1;off<32;off<<=1){
    int y=__shfl_up_sync(0xffffffffu,x,off);
    if((t&31)>=off) x+=y;
  }
  __shared__ int ws[8];
  if((t&31)==31) ws[t>>5]=x;
  __syncthreads();
  if(t==0){ int s=0; for(int j=0;j<8;j++){int tmp=ws[j]; ws[j]=s; s+=tmp;} g_part[b]=s; }
  __syncthreads();
  if(i<NN) g_rowptr[i]= x - v + ws[t>>5];
}
__global__ void k_scan2(int nblk){
  int t=threadIdx.x;
  __shared__ int sh[256];
  sh[t]=(t<nblk)?g_part[t]:0;
  __syncthreads();
  if(t==0){ int s=0; for(int j=0;j<nblk;j++){int tmp=sh[j]; sh[j]=s; s+=tmp;} g_rowptr[NN]=s; }
  __syncthreads();
  if(t<nblk) g_part[t]=sh[t];
}
__global__ void k_scan3(){
  int i=blockIdx.x*blockDim.x+threadIdx.x;
  if(i<NN) g_rowptr[i]+=g_part[i>>8];
}

__global__ void k_prep(){
  int i=blockIdx.x*blockDim.x+threadIdx.x;
  if(i<NN){ g_cursor[i]=g_rowptr[i]; g_inv[i]=rsqrtf((float)g_deg[i]+1.0f); }
}

__global__ void k_scatter(const int* __restrict__ src, const int* __restrict__ dst){
  int e=blockIdx.x*blockDim.x+threadIdx.x;
  if(e>=EE) return;
  int d=dst[e];
  int p=atomicAdd(&g_cursor[d],1);
  g_csrsrc[p]=src[e];
}

// ---------------- aggregation with fused inv scaling + tf32 split ----------------
// agg[i] = inv_i*(inv_i*h[i] + sum_{e:dst=i} inv_src*h[src]); hi/lo tf32 split output
template<int V>
__global__ void k_agg(const float* __restrict__ h, float* __restrict__ ah, float* __restrict__ al){
  int warp=blockIdx.x*(blockDim.x>>5) + (threadIdx.x>>5);
  int lane=threadIdx.x&31;
  if(warp>=NN) return;
  const float4* h4=(const float4*)h;
  size_t base=(size_t)warp*(32*V);
  float wi=g_inv[warp];
  float4 acc[V];
  #pragma unroll
  for(int v=0;v<V;v++){
    float4 q=h4[base+v*32+lane];
    acc[v].x=q.x*wi; acc[v].y=q.y*wi; acc[v].z=q.z*wi; acc[v].w=q.w*wi;
  }
  int s=g_rowptr[warp], e=g_rowptr[warp+1];
  for(int t=s;t<e;t++){
    int src=g_csrsrc[t];
    float ws=g_inv[src];
    const float4* r=h4+(size_t)src*(32*V);
    #pragma unroll
    for(int v=0;v<V;v++){
      float4 q=r[v*32+lane];
      acc[v].x=fmaf(q.x,ws,acc[v].x);
      acc[v].y=fmaf(q.y,ws,acc[v].y);
      acc[v].z=fmaf(q.z,ws,acc[v].z);
      acc[v].w=fmaf(q.w,ws,acc[v].w);
    }
  }
  float4* ah4=(float4*)ah; float4* al4=(float4*)al;
  #pragma unroll
  for(int v=0;v<V;v++){
    float f[4]={acc[v].x*wi, acc[v].y*wi, acc[v].z*wi, acc[v].w*wi};
    float4 hi,lo;
    hi.x=to_tf32(f[0]); lo.x=to_tf32(f[0]-hi.x);
    hi.y=to_tf32(f[1]); lo.y=to_tf32(f[1]-hi.y);
    hi.z=to_tf32(f[2]); lo.z=to_tf32(f[2]-hi.z);
    hi.w=to_tf32(f[3]); lo.w=to_tf32(f[3]-hi.w);
    ah4[base+v*32+lane]=hi;
    al4[base+v*32+lane]=lo;
  }
}

// transpose + split W[Min][Kout] -> Wt_hi/Wt_lo [Kout][Min]
__global__ void k_wsplit(const float* __restrict__ W, int Min, int Kout){
  int idx=blockIdx.x*blockDim.x+threadIdx.x;
  if(idx>=Min*Kout) return;
  int m=idx/Kout, nk=idx-m*Kout;
  float w=W[idx];
  float hi=to_tf32(w);
  float lo=to_tf32(w-hi);
  g_Wth[(size_t)nk*Min+m]=hi;
  g_Wtl[(size_t)nk*Min+m]=lo;
}

// ---------------- tf32 split-3 mma.sync GEMM ----------------
// CTA tile 128(m) x 128(n); 8 warps 4m x 2n; warp tile 32x64; K chunks of 32.
#define PAD 36
__global__ __launch_bounds__(256,2) void k_mma(
    const float* __restrict__ Ah, const float* __restrict__ Al,
    const float* __restrict__ Bh, const float* __restrict__ Bl,
    const float* __restrict__ bias, float* __restrict__ C,
    int n, int Min, int Kout)
{
  extern __shared__ float sm[];
  float* As_h = sm;                    // 128*PAD
  float* As_l = As_h + 128*PAD;
  float* Bs_h = As_l + 128*PAD;        // 128*PAD
  float* Bs_l = Bs_h + 128*PAD;
  uint32_t s_ah=smem_u32(As_h), s_al=smem_u32(As_l);
  uint32_t s_bh=smem_u32(Bs_h), s_bl=smem_u32(Bs_l);

  int tid=threadIdx.x, lane=tid&31, wid=tid>>5;
  int wm = wid&3, wn = wid>>2;         // 4x2 warp grid
  int bm = blockIdx.y*128, bn = blockIdx.x*128;

  float acc[2][8][4];
  #pragma unroll
  for(int a=0;a<2;a++)
    #pragma unroll
    for(int b=0;b<8;b++)
      #pragma unroll
      for(int c=0;c<4;c++) acc[a][b][c]=0.f;

  for(int k0=0;k0<Min;k0+=32){
    // A tiles: 128 rows x 32 cols (h + l) = 1024 float4 each
    #pragma unroll
    for(int it=0;it<4;it++){
      int i=tid+it*256; int r=i>>3, c4=(i&7)*4;
      int grow=bm+r;
      uint32_t soff=(uint32_t)(r*PAD+c4)*4;
      uint32_t sz=(grow<n)?16u:0u;
      const char* gah=(const char*)&Ah[(size_t)grow*Min+k0+c4];
      const char* gal=(const char*)&Al[(size_t)grow*Min+k0+c4];
      cpa16(s_ah+soff, (grow<n)?gah:(const char*)Ah, sz);
      cpa16(s_al+soff, (grow<n)?gal:(const char*)Al, sz);
    }
    // B tiles: 128 rows x 32 cols (h + l)
    #pragma unroll
    for(int it=0;it<4;it++){
      int i=tid+it*256; int r=i>>3, c4=(i&7)*4;
      int brow=bn+r;
      uint32_t soff=(uint32_t)(r*PAD+c4)*4;
      cpa16f(s_bh+soff, &Bh[(size_t)brow*Min+k0+c4]);
      cpa16f(s_bl+soff, &Bl[(size_t)brow*Min+k0+c4]);
    }
    CPA_COMMIT();
    CPA_WAIT0();
    __syncthreads();

    #pragma unroll
    for(int ks=0;ks<4;ks++){
      int kk=ks*8;
      uint32_t afh[2][4], afl[2][4];
      int ar = wm*32 + (lane>>2), ac = kk + (lane&3);
      #pragma unroll
      for(int mf=0;mf<2;mf++){
        int r0 = ar + mf*16;
        afh[mf][0]=__float_as_uint(As_h[r0*PAD+ac]);
        afh[mf][1]=__float_as_uint(As_h[(r0+8)*PAD+ac]);
        afh[mf][2]=__float_as_uint(As_h[r0*PAD+ac+4]);
        afh[mf][3]=__float_as_uint(As_h[(r0+8)*PAD+ac+4]);
        afl[mf][0]=__float_as_uint(As_l[r0*PAD+ac]);
        afl[mf][1]=__float_as_uint(As_l[(r0+8)*PAD+ac]);
        afl[mf][2]=__float_as_uint(As_l[r0*PAD+ac+4]);
        afl[mf][3]=__float_as_uint(As_l[(r0+8)*PAD+ac+4]);
      }
      #pragma unroll
      for(int nf=0;nf<8;nf++){
        int bn_r = wn*64 + nf*8 + (lane>>2);
        int bk = kk + (lane&3);
        uint32_t bh0=__float_as_uint(Bs_h[bn_r*PAD+bk]);
        uint32_t bh1=__float_as_uint(Bs_h[bn_r*PAD+bk+4]);
        uint32_t bl0=__float_as_uint(Bs_l[bn_r*PAD+bk]);
        uint32_t bl1=__float_as_uint(Bs_l[bn_r*PAD+bk+4]);
        #pragma unroll
        for(int mf=0;mf<2;mf++){
          mma8(acc[mf][nf], afh[mf], bh0, bh1);
          mma8(acc[mf][nf], afh[mf], bl0, bl1);
          mma8(acc[mf][nf], afl[mf], bh0, bh1);
        }
      }
    }
    __syncthreads();
  }

  // epilogue: bias + relu, float2 stores
  #pragma unroll
  for(int mf=0;mf<2;mf++){
    int row0 = bm + wm*32 + mf*16 + (lane>>2);
    #pragma unroll
    for(int nf=0;nf<8;nf++){
      int col = bn + wn*64 + nf*8 + (lane&3)*2;
      float b0v=bias[col], b1v=bias[col+1];
      if(row0<n){
        float2 v; v.x=fmaxf(acc[mf][nf][0]+b0v,0.f); v.y=fmaxf(acc[mf][nf][1]+b1v,0.f);
        *(float2*)&C[(size_t)row0*Kout+col]=v;
      }
      if(row0+8<n){
        float2 v; v.x=fmaxf(acc[mf][nf][2]+b0v,0.f); v.y=fmaxf(acc[mf][nf][3]+b1v,0.f);
        *(float2*)&C[(size_t)(row0+8)*Kout+col]=v;
      }
    }
  }
}
#define MMA_SMEM (4*128*PAD*4)

// ---------------- softmax + argmax (warp per row of 512) ----------------
__global__ void k_softmax(const float* __restrict__ h, float* __restrict__ S){
  int warp=blockIdx.x*(blockDim.x>>5)+(threadIdx.x>>5);
  int lane=threadIdx.x&31;
  if(warp>=NN) return;
  const float* row=h+(size_t)warp*CC;
  float vals[16];
  float m=-3.4e38f; int am=0;
  #pragma unroll
  for(int c=0;c<16;c++){
    float v=row[c*32+lane];
    vals[c]=v;
    if(v>m){m=v;am=c*32+lane;}
  }
  #pragma unroll
  for(int off=16;off>0;off>>=1){
    float om=__shfl_down_sync(0xffffffffu,m,off);
    int   oa=__shfl_down_sync(0xffffffffu,am,off);
    if(om>m || (om==m && oa<am)){m=om;am=oa;}
  }
  m=__shfl_sync(0xffffffffu,m,0);
  am=__shfl_sync(0xffffffffu,am,0);
  float s=0.f;
  #pragma unroll
  for(int c=0;c<16;c++){ vals[c]=expf(vals[c]-m); s+=vals[c]; }
  #pragma unroll
  for(int off=16;off>0;off>>=1) s+=__shfl_down_sync(0xffffffffu,s,off);
  s=__shfl_sync(0xffffffffu,s,0);
  float invs=1.f/s;
  float* so=S+(size_t)warp*CC;
  #pragma unroll
  for(int c=0;c<16;c++) so[c*32+lane]=vals[c]*invs;
  if(lane==0) g_cluster[warp]=am;
}

// ---------------- score branch ----------------
__global__ void k_hs(const float* __restrict__ x, const float* __restrict__ Wsm){
  int warp=blockIdx.x*(blockDim.x>>5)+(threadIdx.x>>5);
  int lane=threadIdx.x&31;
  if(warp>=NN) return;
  float4 v=((const float4*)x)[(size_t)warp*32+lane];
  float4 w=((const float4*)Wsm)[lane];
  float d=v.x*w.x+v.y*w.y+v.z*w.z+v.w*w.w;
  #pragma unroll
  for(int off=16;off>0;off>>=1) d+=__shfl_down_sync(0xffffffffu,d,off);
  if(lane==0) g_hs[warp]=d;
}

__global__ void k_degs(){
  int i=blockIdx.x*blockDim.x+threadIdx.x;
  if(i>=NN) return;
  int ci=g_cluster[i];
  int s=g_rowptr[i], e=g_rowptr[i+1], cnt=0;
  for(int t=s;t<e;t++) cnt += (g_cluster[g_csrsrc[t]]==ci) ? 1 : 0;
  g_invs[i]=rsqrtf((float)cnt+1.0f);
  if(cnt>0) atomicAdd(&g_cintra[ci],cnt);
}

__global__ void k_score(const float* __restrict__ bs){
  int i=blockIdx.x*blockDim.x+threadIdx.x;
  if(i>=NN) return;
  int ci=g_cluster[i];
  int s=g_rowptr[i], e=g_rowptr[i+1];
  float sum=0.f;
  for(int t=s;t<e;t++){
    int sn=g_csrsrc[t];
    if(g_cluster[sn]==ci) sum += g_invs[sn]*g_hs[sn];
  }
  float w=g_invs[i];
  g_score[i]=tanhf(w*(sum + w*g_hs[i]) + bs[0]);
}

__global__ void k_segmax(){
  int i=blockIdx.x*blockDim.x+threadIdx.x;
  if(i<NN) atomicMax(&g_segkey[g_cluster[i]], fenc(g_score[i]));
}

__global__ void k_argnode(){
  int i=blockIdx.x*blockDim.x+threadIdx.x;
  if(i>=NN) return;
  int c=g_cluster[i];
  if(fenc(g_score[i]) >= g_segkey[c]) atomicMin(&g_segidx[c], i);
}

// ---------------- outputs ----------------
__global__ void k_newx(const float* __restrict__ x, float* __restrict__ out){
  int c=blockIdx.x;
  int t=threadIdx.x;
  __shared__ float alpha; __shared__ int idx;
  if(t==0){
    alpha = (g_cintra[c]>0) ? fdec(g_segkey[c]) : 0.f;
    idx = min(g_segidx[c], NN-1);
  }
  __syncthreads();
  out[OFF_NEWX + c*FF + t] = x[(size_t)idx*FF + t]*alpha;
}

__global__ void k_adjzero(float* __restrict__ out){
  int i=blockIdx.x*blockDim.x+threadIdx.x;
  if(i<CC*CC+CC) out[OFF_ADJ+i]=0.f;
}

__global__ void k_adjfill(const int* __restrict__ src, const int* __restrict__ dst, float* __restrict__ out){
  int e=blockIdx.x*blockDim.x+threadIdx.x;
  if(e>=EE) return;
  int ci=g_cluster[src[e]], cj=g_cluster[dst[e]];
  if(ci!=cj && g_cintra[ci]>0 && g_cintra[cj]>0)
    out[OFF_ADJ + ci*CC + cj]=1.0f;
}

// ---------------- launch ----------------
extern "C" void kernel_launch(void* const* d_in, const int* in_sizes, int n_in,
                              void* d_out, int out_size)
{
  const float* x  =(const float*)d_in[0];
  const int*   ei =(const int*)  d_in[1];
  const float* W1 =(const float*)d_in[3];
  const float* b1 =(const float*)d_in[4];
  const float* W2 =(const float*)d_in[5];
  const float* b2 =(const float*)d_in[6];
  const float* W3 =(const float*)d_in[7];
  const float* b3 =(const float*)d_in[8];
  const float* Wsm=(const float*)d_in[9];
  const float* bs =(const float*)d_in[10];
  float* out=(float*)d_out;

  const int* srcp=ei;
  const int* dstp=ei+EE;

  float *p_h,*p_ah,*p_al,*p_wh,*p_wl;
  cudaGetSymbolAddress((void**)&p_h,  g_h);
  cudaGetSymbolAddress((void**)&p_ah, g_Ah);
  cudaGetSymbolAddress((void**)&p_al, g_Al);
  cudaGetSymbolAddress((void**)&p_wh, g_Wth);
  cudaGetSymbolAddress((void**)&p_wl, g_Wtl);

  cudaFuncSetAttribute(k_mma, cudaFuncAttributeMaxDynamicSharedMemorySize, MMA_SMEM);

  const int TB=256;
  const int gN=(NN+TB-1)/TB;       // 196
  const int gE=(EE+TB-1)/TB;
  const int gW=(NN+7)/8;
  const int gM=(NN+127)/128;       // 391

  // graph prep
  k_init<<<gN,TB>>>();
  k_deg<<<gE,TB>>>(dstp);
  k_scan1<<<gN,TB>>>();
  k_scan2<<<1,256>>>(gN);
  k_scan3<<<gN,TB>>>();
  k_prep<<<gN,TB>>>();
  k_scatter<<<gE,TB>>>(srcp,dstp);

  // layer 1: F=128 -> 256
  k_wsplit<<<(128*256+TB-1)/TB,TB>>>(W1,128,256);
  k_agg<1><<<gW,TB>>>(x,p_ah,p_al);
  k_mma<<<dim3(2,gM),256,MMA_SMEM>>>(p_ah,p_al,p_wh,p_wl,b1,p_h,NN,128,256);

  // layer 2: 256 -> 256
  k_wsplit<<<(256*256+TB-1)/TB,TB>>>(W2,256,256);
  k_agg<2><<<gW,TB>>>(p_h,p_ah,p_al);
  k_mma<<<dim3(2,gM),256,MMA_SMEM>>>(p_ah,p_al,p_wh,p_wl,b2,p_h,NN,256,256);

  // layer 3: 256 -> 512
  k_wsplit<<<(256*512+TB-1)/TB,TB>>>(W3,256,512);
  k_agg<2><<<gW,TB>>>(p_h,p_ah,p_al);
  k_mma<<<dim3(4,gM),256,MMA_SMEM>>>(p_ah,p_al,p_wh,p_wl,b3,p_h,NN,256,512);

  // softmax S + hard cluster assignment
  k_softmax<<<gW,TB>>>(p_h, out+OFF_S);

  // score branch
  k_hs<<<gW,TB>>>(x,Wsm);
  k_degs<<<gN,TB>>>();
  k_score<<<gN,TB>>>(bs);
  k_segmax<<<gN,TB>>>();
  k_argnode<<<gN,TB>>>();

  // outputs
  k_newx<<<CC,FF>>>(x,out);
  k_adjzero<<<(CC*CC+CC+TB-1)/TB,TB>>>(out);
  k_adjfill<<<gE,TB>>>(srcp,dstp,out);
}